// round 1
// baseline (speedup 1.0000x reference)
#include <cuda_runtime.h>
#include <cuda_bf16.h>

// Problem constants (from reference: z [8,256,4096] f32, emb [8192,256] f32)
#define B_ 8
#define D_ 256
#define T_ 4096
#define N_ 32768   // B*T tokens
#define K_ 8192    // codebook size

// Scratch (device globals — no allocation allowed)
__device__ int   g_idx[N_];
__device__ float g_z2[N_];
__device__ float g_e2[K_];
__device__ float g_lpart[N_];

// ---------------------------------------------------------------------------
// z2[n] = sum_d fl(z[b,d,t]^2), strictly sequential in d (match XLA CPU reduce)
// ---------------------------------------------------------------------------
__global__ void k_z2(const float* __restrict__ z) {
    int n = blockIdx.x * blockDim.x + threadIdx.x;
    if (n >= N_) return;
    int b = n >> 12, t = n & 4095;
    const float* p = z + (size_t)b * D_ * T_ + t;
    float s = 0.0f;
    #pragma unroll 8
    for (int d = 0; d < D_; d++) {
        float v = p[(size_t)d * T_];
        s = __fadd_rn(s, __fmul_rn(v, v));   // rounded square, then in-order add
    }
    g_z2[n] = s;
}

__global__ void k_e2(const float* __restrict__ emb) {
    int k = blockIdx.x * blockDim.x + threadIdx.x;
    if (k >= K_) return;
    const float* p = emb + (size_t)k * D_;
    float s = 0.0f;
    #pragma unroll 8
    for (int d = 0; d < D_; d++) {
        float v = __ldg(p + d);
        s = __fadd_rn(s, __fmul_rn(v, v));
    }
    g_e2[k] = s;
}

// ---------------------------------------------------------------------------
// Fused distance-GEMM + argmin.
// Block: 128 tokens (one contiguous t-range inside one b), loops all K codes.
// 256 threads, 8x8 micro-tile (split 4+4 fragments for bank-friendly LDS.128).
// d_k = fl( fl(z2 + e2_k) - fl(2 * dot(z,e_k)) )  — replicates reference rounding.
// ---------------------------------------------------------------------------
#define TM 128
#define TK 128
#define DC 32

__global__ __launch_bounds__(256, 2)
void k_main(const float* __restrict__ z, const float* __restrict__ emb) {
    __shared__ float zs[DC * TM];   // 16 KB, d-major: zs[dd*TM + m]
    __shared__ float es[DC * TK];   // 16 KB, d-major: es[dd*TK + kk]

    int tid = threadIdx.x;
    int tm = tid & 15;        // token sub-tile (fast within warp)
    int tn = tid >> 4;        // code sub-tile
    int n0 = blockIdx.x * TM;
    int b = n0 >> 12, t0 = n0 & 4095;   // 4096 % 128 == 0 -> tile within one b
    const float* zbase = z + (size_t)b * D_ * T_ + t0;

    float best[8];
    int   bidx[8];
    float z2r[8];
    #pragma unroll
    for (int i = 0; i < 8; i++) {
        best[i] = 3.4e38f;
        bidx[i] = 0;
        int m = (i < 4) ? (tm * 4 + i) : (64 + tm * 4 + (i - 4));
        z2r[i] = g_z2[n0 + m];
    }

    for (int k0 = 0; k0 < K_; k0 += TK) {
        float acc[8][8];
        #pragma unroll
        for (int i = 0; i < 8; i++)
            #pragma unroll
            for (int j = 0; j < 8; j++) acc[i][j] = 0.0f;

        for (int d0 = 0; d0 < D_; d0 += DC) {
            // --- load z tile: 32 x 128 floats, fully coalesced float4 ---
            #pragma unroll
            for (int c = 0; c < 4; c++) {
                int p  = tid + c * 256;   // float4 slot 0..1023
                int dd = p >> 5;          // 32 float4 per row
                int m4 = p & 31;
                float4 v = *(const float4*)(zbase + (size_t)(d0 + dd) * T_ + m4 * 4);
                *(float4*)&zs[dd * TM + m4 * 4] = v;
            }
            // --- load e tile transposed (emb is k-major): L2-resident reads ---
            {
                int kk   = tid & 127;
                int half = tid >> 7;
                #pragma unroll
                for (int c = 0; c < 4; c++) {
                    int c4 = half * 4 + c;   // 0..7 float4 chunks of the 32-wide row
                    float4 v = *(const float4*)(emb + (size_t)(k0 + kk) * D_ + d0 + c4 * 4);
                    es[(c4 * 4 + 0) * TK + kk] = v.x;
                    es[(c4 * 4 + 1) * TK + kk] = v.y;
                    es[(c4 * 4 + 2) * TK + kk] = v.z;
                    es[(c4 * 4 + 3) * TK + kk] = v.w;
                }
            }
            __syncthreads();

            #pragma unroll
            for (int dd = 0; dd < DC; dd++) {
                float za[8], eb[8];
                *(float4*)&za[0] = *(const float4*)&zs[dd * TM + tm * 4];
                *(float4*)&za[4] = *(const float4*)&zs[dd * TM + 64 + tm * 4];
                *(float4*)&eb[0] = *(const float4*)&es[dd * TK + tn * 4];
                *(float4*)&eb[4] = *(const float4*)&es[dd * TK + 64 + tn * 4];
                #pragma unroll
                for (int i = 0; i < 8; i++)
                    #pragma unroll
                    for (int j = 0; j < 8; j++)
                        acc[i][j] = fmaf(za[i], eb[j], acc[i][j]);
            }
            __syncthreads();
        }

        // --- score this code chunk, update running argmin (k ascending) ---
        float e2r[8];
        #pragma unroll
        for (int j = 0; j < 8; j++) {
            int kc = (j < 4) ? (tn * 4 + j) : (64 + tn * 4 + (j - 4));
            e2r[j] = g_e2[k0 + kc];
        }
        #pragma unroll
        for (int i = 0; i < 8; i++) {
            #pragma unroll
            for (int j = 0; j < 8; j++) {
                int kc = (j < 4) ? (tn * 4 + j) : (64 + tn * 4 + (j - 4));
                int k  = k0 + kc;
                // exact reference rounding: fl(fl(z2+e2) - fl(2*ze))
                float dv = __fsub_rn(__fadd_rn(z2r[i], e2r[j]),
                                     __fmul_rn(2.0f, acc[i][j]));
                if (dv < best[i]) { best[i] = dv; bidx[i] = k; }  // strict < : first index wins
            }
        }
    }

    // --- cross-thread argmin per token row (reuse smem) ---
    __syncthreads();
    float* sval = zs;                  // 16 x 128 floats
    int*   sidx = (int*)es;
    #pragma unroll
    for (int i = 0; i < 8; i++) {
        int m = (i < 4) ? (tm * 4 + i) : (64 + tm * 4 + (i - 4));
        sval[tn * TM + m] = best[i];
        sidx[tn * TM + m] = bidx[i];
    }
    __syncthreads();
    if (tid < TM) {
        float bv = 3.4e38f;
        int   bi = 0x7fffffff;
        #pragma unroll
        for (int s = 0; s < 16; s++) {
            float v  = sval[s * TM + tid];
            int   id = sidx[s * TM + tid];
            if (v < bv || (v == bv && id < bi)) { bv = v; bi = id; }  // lexicographic: first index on tie
        }
        g_idx[n0 + tid] = bi;
    }
}

// ---------------------------------------------------------------------------
// Gather z_q = emb[idx] back to [B,D,T]; per-token loss partials; optional idx.
// ---------------------------------------------------------------------------
__global__ void k_out(const float* __restrict__ z, const float* __restrict__ emb,
                      float* __restrict__ out, int write_zq, int write_idx, int idx_off) {
    int n = blockIdx.x * blockDim.x + threadIdx.x;
    if (n >= N_) return;
    int b = n >> 12, t = n & 4095;
    int idx = g_idx[n];
    const float* e  = emb + (size_t)idx * D_;            // L2-resident row
    const float* zp = z   + (size_t)b * D_ * T_ + t;
    float* op       = out + (size_t)b * D_ * T_ + t;
    float s = 0.0f;
    #pragma unroll 8
    for (int d = 0; d < D_; d++) {
        float ev = __ldg(e + d);
        float zv = zp[(size_t)d * T_];
        float df = ev - zv;
        s = fmaf(df, df, s);
        if (write_zq) op[(size_t)d * T_] = ev;           // coalesced over t
    }
    g_lpart[n] = s;
    if (write_idx) out[idx_off + n] = (float)idx;
}

// Deterministic fixed-order loss reduction (no atomics)
__global__ void k_loss(float* __restrict__ out, int loss_off) {
    __shared__ float sm[1024];
    int tid = threadIdx.x;
    float s = 0.0f;
    #pragma unroll 4
    for (int i = 0; i < 32; i++) s += g_lpart[tid * 32 + i];
    sm[tid] = s;
    __syncthreads();
    for (int w = 512; w > 0; w >>= 1) {
        if (tid < w) sm[tid] += sm[tid + w];
        __syncthreads();
    }
    if (tid == 0)
        out[loss_off] = 1.25f * (sm[0] / 8388608.0f);   // (1+beta) * mean((zq - z)^2)
}

// ---------------------------------------------------------------------------
extern "C" void kernel_launch(void* const* d_in, const int* in_sizes, int n_in,
                              void* d_out, int out_size) {
    const float* z   = (const float*)d_in[0];
    const float* emb = (const float*)d_in[1];
    // Defensive: identify by size if order differs from metadata expectation
    if (n_in >= 2 && in_sizes[0] == K_ * D_ && in_sizes[1] == N_ * D_) {
        z   = (const float*)d_in[1];
        emb = (const float*)d_in[0];
    }
    float* out = (float*)d_out;

    k_z2<<<N_ / 256, 256>>>(z);
    k_e2<<<K_ / 256, 256>>>(emb);
    k_main<<<N_ / TM, 256>>>(z, emb);

    const int ZQ = N_ * D_;  // 8388608
    if (out_size == N_) {
        // idx-only layout
        k_out<<<N_ / 256, 256>>>(z, emb, out, 0, 1, 0);
    } else {
        int write_zq  = (out_size >= ZQ) ? 1 : 0;
        int write_loss = 0, write_idx = 0, idx_off = ZQ;
        if (out_size >= ZQ + 1 + N_) { write_loss = 1; write_idx = 1; idx_off = ZQ + 1; }
        else if (out_size == ZQ + N_) { write_idx = 1; idx_off = ZQ; }
        else if (out_size >= ZQ + 1) { write_loss = 1; }
        k_out<<<N_ / 256, 256>>>(z, emb, out, write_zq, write_idx, idx_off);
        if (write_loss) k_loss<<<1, 1024>>>(out, ZQ);
    }
}

// round 2
// speedup vs baseline: 1.0050x; 1.0050x over previous
#include <cuda_runtime.h>
#include <cuda_bf16.h>

// Problem constants (from reference: z [8,256,4096] f32, emb [8192,256] f32)
#define B_ 8
#define D_ 256
#define T_ 4096
#define N_ 32768   // B*T tokens
#define K_ 8192    // codebook size

// Scratch (device globals — no allocation allowed)
__device__ int   g_idx[N_];
__device__ float g_z2[N_];
__device__ float g_e2[K_];
__device__ float g_lpart[N_];

// ---------------------------------------------------------------------------
// z2[n] = sum_d fl(z[b,d,t]^2), strictly sequential in d (match XLA CPU reduce)
// ---------------------------------------------------------------------------
__global__ void k_z2(const float* __restrict__ z) {
    int n = blockIdx.x * blockDim.x + threadIdx.x;
    if (n >= N_) return;
    int b = n >> 12, t = n & 4095;
    const float* p = z + (size_t)b * D_ * T_ + t;
    float s = 0.0f;
    #pragma unroll 8
    for (int d = 0; d < D_; d++) {
        float v = p[(size_t)d * T_];
        s = __fadd_rn(s, __fmul_rn(v, v));   // rounded square, then in-order add
    }
    g_z2[n] = s;
}

__global__ void k_e2(const float* __restrict__ emb) {
    int k = blockIdx.x * blockDim.x + threadIdx.x;
    if (k >= K_) return;
    const float* p = emb + (size_t)k * D_;
    float s = 0.0f;
    #pragma unroll 8
    for (int d = 0; d < D_; d++) {
        float v = __ldg(p + d);
        s = __fadd_rn(s, __fmul_rn(v, v));
    }
    g_e2[k] = s;
}

// ---------------------------------------------------------------------------
// Fused distance-GEMM + argmin.
// Block: 128 tokens (one contiguous t-range inside one b), loops all K codes.
// 256 threads, 8x8 micro-tile (split 4+4 fragments for bank-friendly LDS.128).
// d_k = fl( fl(z2 + e2_k) - fl(2 * dot(z,e_k)) )  — replicates reference rounding.
// ---------------------------------------------------------------------------
#define TM 128
#define TK 128
#define DC 32

__global__ __launch_bounds__(256, 2)
void k_main(const float* __restrict__ z, const float* __restrict__ emb) {
    __shared__ float zs[DC * TM];   // 16 KB, d-major: zs[dd*TM + m]
    __shared__ float es[DC * TK];   // 16 KB, d-major: es[dd*TK + kk]

    int tid = threadIdx.x;
    int tm = tid & 15;        // token sub-tile (fast within warp)
    int tn = tid >> 4;        // code sub-tile
    int n0 = blockIdx.x * TM;
    int b = n0 >> 12, t0 = n0 & 4095;   // 4096 % 128 == 0 -> tile within one b
    const float* zbase = z + (size_t)b * D_ * T_ + t0;

    float best[8];
    int   bidx[8];
    float z2r[8];
    #pragma unroll
    for (int i = 0; i < 8; i++) {
        best[i] = 3.4e38f;
        bidx[i] = 0;
        int m = (i < 4) ? (tm * 4 + i) : (64 + tm * 4 + (i - 4));
        z2r[i] = g_z2[n0 + m];
    }

    for (int k0 = 0; k0 < K_; k0 += TK) {
        float acc[8][8];
        #pragma unroll
        for (int i = 0; i < 8; i++)
            #pragma unroll
            for (int j = 0; j < 8; j++) acc[i][j] = 0.0f;

        for (int d0 = 0; d0 < D_; d0 += DC) {
            // --- load z tile: 32 x 128 floats, fully coalesced float4 ---
            #pragma unroll
            for (int c = 0; c < 4; c++) {
                int p  = tid + c * 256;   // float4 slot 0..1023
                int dd = p >> 5;          // 32 float4 per row
                int m4 = p & 31;
                float4 v = *(const float4*)(zbase + (size_t)(d0 + dd) * T_ + m4 * 4);
                *(float4*)&zs[dd * TM + m4 * 4] = v;
            }
            // --- load e tile transposed (emb is k-major): L2-resident reads ---
            {
                int kk   = tid & 127;
                int half = tid >> 7;
                #pragma unroll
                for (int c = 0; c < 4; c++) {
                    int c4 = half * 4 + c;   // 0..7 float4 chunks of the 32-wide row
                    float4 v = *(const float4*)(emb + (size_t)(k0 + kk) * D_ + d0 + c4 * 4);
                    es[(c4 * 4 + 0) * TK + kk] = v.x;
                    es[(c4 * 4 + 1) * TK + kk] = v.y;
                    es[(c4 * 4 + 2) * TK + kk] = v.z;
                    es[(c4 * 4 + 3) * TK + kk] = v.w;
                }
            }
            __syncthreads();

            #pragma unroll
            for (int dd = 0; dd < DC; dd++) {
                float za[8], eb[8];
                *(float4*)&za[0] = *(const float4*)&zs[dd * TM + tm * 4];
                *(float4*)&za[4] = *(const float4*)&zs[dd * TM + 64 + tm * 4];
                *(float4*)&eb[0] = *(const float4*)&es[dd * TK + tn * 4];
                *(float4*)&eb[4] = *(const float4*)&es[dd * TK + 64 + tn * 4];
                #pragma unroll
                for (int i = 0; i < 8; i++)
                    #pragma unroll
                    for (int j = 0; j < 8; j++)
                        acc[i][j] = fmaf(za[i], eb[j], acc[i][j]);
            }
            __syncthreads();
        }

        // --- score this code chunk, update running argmin (k ascending) ---
        float e2r[8];
        #pragma unroll
        for (int j = 0; j < 8; j++) {
            int kc = (j < 4) ? (tn * 4 + j) : (64 + tn * 4 + (j - 4));
            e2r[j] = g_e2[k0 + kc];
        }
        #pragma unroll
        for (int i = 0; i < 8; i++) {
            #pragma unroll
            for (int j = 0; j < 8; j++) {
                int kc = (j < 4) ? (tn * 4 + j) : (64 + tn * 4 + (j - 4));
                int k  = k0 + kc;
                // exact reference rounding: fl(fl(z2+e2) - fl(2*ze))
                float dv = __fsub_rn(__fadd_rn(z2r[i], e2r[j]),
                                     __fmul_rn(2.0f, acc[i][j]));
                if (dv < best[i]) { best[i] = dv; bidx[i] = k; }  // strict < : first index wins
            }
        }
    }

    // --- cross-thread argmin per token row (reuse smem) ---
    __syncthreads();
    float* sval = zs;                  // 16 x 128 floats
    int*   sidx = (int*)es;
    #pragma unroll
    for (int i = 0; i < 8; i++) {
        int m = (i < 4) ? (tm * 4 + i) : (64 + tm * 4 + (i - 4));
        sval[tn * TM + m] = best[i];
        sidx[tn * TM + m] = bidx[i];
    }
    __syncthreads();
    if (tid < TM) {
        float bv = 3.4e38f;
        int   bi = 0x7fffffff;
        #pragma unroll
        for (int s = 0; s < 16; s++) {
            float v  = sval[s * TM + tid];
            int   id = sidx[s * TM + tid];
            if (v < bv || (v == bv && id < bi)) { bv = v; bi = id; }  // lexicographic: first index on tie
        }
        g_idx[n0 + tid] = bi;
    }
}

// ---------------------------------------------------------------------------
// Gather z_q = emb[idx] back to [B,D,T]; per-token loss partials; optional idx.
// ---------------------------------------------------------------------------
__global__ void k_out(const float* __restrict__ z, const float* __restrict__ emb,
                      float* __restrict__ out, int write_zq, int write_idx, int idx_off) {
    int n = blockIdx.x * blockDim.x + threadIdx.x;
    if (n >= N_) return;
    int b = n >> 12, t = n & 4095;
    int idx = g_idx[n];
    const float* e  = emb + (size_t)idx * D_;            // L2-resident row
    const float* zp = z   + (size_t)b * D_ * T_ + t;
    float* op       = out + (size_t)b * D_ * T_ + t;
    float s = 0.0f;
    #pragma unroll 8
    for (int d = 0; d < D_; d++) {
        float ev = __ldg(e + d);
        float zv = zp[(size_t)d * T_];
        float df = ev - zv;
        s = fmaf(df, df, s);
        if (write_zq) op[(size_t)d * T_] = ev;           // coalesced over t
    }
    g_lpart[n] = s;
    if (write_idx) out[idx_off + n] = (float)idx;
}

// Deterministic fixed-order loss reduction (no atomics)
__global__ void k_loss(float* __restrict__ out, int loss_off) {
    __shared__ float sm[1024];
    int tid = threadIdx.x;
    float s = 0.0f;
    #pragma unroll 4
    for (int i = 0; i < 32; i++) s += g_lpart[tid * 32 + i];
    sm[tid] = s;
    __syncthreads();
    for (int w = 512; w > 0; w >>= 1) {
        if (tid < w) sm[tid] += sm[tid + w];
        __syncthreads();
    }
    if (tid == 0)
        out[loss_off] = 1.25f * (sm[0] / 8388608.0f);   // (1+beta) * mean((zq - z)^2)
}

// ---------------------------------------------------------------------------
extern "C" void kernel_launch(void* const* d_in, const int* in_sizes, int n_in,
                              void* d_out, int out_size) {
    const float* z   = (const float*)d_in[0];
    const float* emb = (const float*)d_in[1];
    // Defensive: identify by size if order differs from metadata expectation
    if (n_in >= 2 && in_sizes[0] == K_ * D_ && in_sizes[1] == N_ * D_) {
        z   = (const float*)d_in[1];
        emb = (const float*)d_in[0];
    }
    float* out = (float*)d_out;

    k_z2<<<N_ / 256, 256>>>(z);
    k_e2<<<K_ / 256, 256>>>(emb);
    k_main<<<N_ / TM, 256>>>(z, emb);

    const int ZQ = N_ * D_;  // 8388608
    if (out_size == N_) {
        // idx-only layout
        k_out<<<N_ / 256, 256>>>(z, emb, out, 0, 1, 0);
    } else {
        int write_zq  = (out_size >= ZQ) ? 1 : 0;
        int write_loss = 0, write_idx = 0, idx_off = ZQ;
        if (out_size >= ZQ + 1 + N_) { write_loss = 1; write_idx = 1; idx_off = ZQ + 1; }
        else if (out_size == ZQ + N_) { write_idx = 1; idx_off = ZQ; }
        else if (out_size >= ZQ + 1) { write_loss = 1; }
        k_out<<<N_ / 256, 256>>>(z, emb, out, write_zq, write_idx, idx_off);
        if (write_loss) k_loss<<<1, 1024>>>(out, ZQ);
    }
}